// round 2
// baseline (speedup 1.0000x reference)
#include <cuda_runtime.h>

// out[w*2048+h] = -dot(weight3x3, x[3w:3w+3, 3h:3h+3]) / 0.924458
// x: 6144x6144 fp32, out: 2048x2048 fp32. Pure HBM stream (168 MB).
// One thread -> 8 adjacent outputs: 24 contiguous floats/row (6 float4 loads)
// x 3 rows = 18 front-batched streaming loads, 2 float4 streaming stores.

#define XW 6144
#define NH 2048
#define GROUPS_PER_ROW 256   // NH / 8

__global__ __launch_bounds__(256) void conv3x3_stride3_kernel(
    const float* __restrict__ x,
    const float* __restrict__ wgt,
    float* __restrict__ out)
{
    int idx = blockIdx.x * blockDim.x + threadIdx.x;   // 0 .. 2048*256-1
    int w = idx >> 8;                 // output row
    int g = idx & (GROUPS_PER_ROW - 1);  // group of 8 outputs

    float k0 = wgt[0], k1 = wgt[1], k2 = wgt[2];
    float k3 = wgt[3], k4 = wgt[4], k5 = wgt[5];
    float k6 = wgt[6], k7 = wgt[7], k8 = wgt[8];
    const float scale = (float)(-1.0 / 0.924458);

    // rows 3w..3w+2, starting col 24*g (96B aligned)
    const float* base = x + (size_t)(3 * w) * XW + 24 * g;

    float4 a[6], b[6], c[6];
#pragma unroll
    for (int i = 0; i < 6; i++) a[i] = __ldcs((const float4*)(base) + i);
#pragma unroll
    for (int i = 0; i < 6; i++) b[i] = __ldcs((const float4*)(base + XW) + i);
#pragma unroll
    for (int i = 0; i < 6; i++) c[i] = __ldcs((const float4*)(base + 2 * XW) + i);

    float r0[24], r1[24], r2[24];
#pragma unroll
    for (int i = 0; i < 6; i++) {
        r0[4*i] = a[i].x; r0[4*i+1] = a[i].y; r0[4*i+2] = a[i].z; r0[4*i+3] = a[i].w;
        r1[4*i] = b[i].x; r1[4*i+1] = b[i].y; r1[4*i+2] = b[i].z; r1[4*i+3] = b[i].w;
        r2[4*i] = c[i].x; r2[4*i+1] = c[i].y; r2[4*i+2] = c[i].z; r2[4*i+3] = c[i].w;
    }

    float res[8];
#pragma unroll
    for (int j = 0; j < 8; j++) {
        res[j] = (k0 * r0[3*j] + k1 * r0[3*j+1] + k2 * r0[3*j+2]
                + k3 * r1[3*j] + k4 * r1[3*j+1] + k5 * r1[3*j+2]
                + k6 * r2[3*j] + k7 * r2[3*j+1] + k8 * r2[3*j+2]) * scale;
    }

    float4 o0 = make_float4(res[0], res[1], res[2], res[3]);
    float4 o1 = make_float4(res[4], res[5], res[6], res[7]);
    // output float4 index: (w*2048 + 8g)/4 = 2*idx
    __stcs((float4*)out + 2 * idx,     o0);
    __stcs((float4*)out + 2 * idx + 1, o1);
}

extern "C" void kernel_launch(void* const* d_in, const int* in_sizes, int n_in,
                              void* d_out, int out_size)
{
    const float* x   = (const float*)d_in[0];
    const float* wgt = (const float*)d_in[1];
    float* out = (float*)d_out;

    int total_threads = NH * GROUPS_PER_ROW;   // 524,288
    int block = 256;
    int grid = total_threads / block;          // 2048
    conv3x3_stride3_kernel<<<grid, block>>>(x, wgt, out);
}

// round 3
// speedup vs baseline: 1.0077x; 1.0077x over previous
#include <cuda_runtime.h>

// out[w*2048+h] = -dot(weight3x3, x[3w:3w+3, 3h:3h+3]) / 0.924458
// x: 6144x6144 fp32, out: 2048x2048 fp32. Pure HBM stream (168 MB).
// One thread -> 8 adjacent outputs: 24 contiguous floats/row (6 float4 loads)
// x 3 rows = 18 front-batched streaming loads, 2 float4 streaming stores.

#define XW 6144
#define NH 2048
#define GROUPS_PER_ROW 256   // NH / 8

__global__ __launch_bounds__(256) void conv3x3_stride3_kernel(
    const float* __restrict__ x,
    const float* __restrict__ wgt,
    float* __restrict__ out)
{
    int idx = blockIdx.x * blockDim.x + threadIdx.x;   // 0 .. 2048*256-1
    int w = idx >> 8;                 // output row
    int g = idx & (GROUPS_PER_ROW - 1);  // group of 8 outputs

    float k0 = wgt[0], k1 = wgt[1], k2 = wgt[2];
    float k3 = wgt[3], k4 = wgt[4], k5 = wgt[5];
    float k6 = wgt[6], k7 = wgt[7], k8 = wgt[8];
    const float scale = (float)(-1.0 / 0.924458);

    // rows 3w..3w+2, starting col 24*g (96B aligned)
    const float* base = x + (size_t)(3 * w) * XW + 24 * g;

    float4 a[6], b[6], c[6];
#pragma unroll
    for (int i = 0; i < 6; i++) a[i] = __ldcs((const float4*)(base) + i);
#pragma unroll
    for (int i = 0; i < 6; i++) b[i] = __ldcs((const float4*)(base + XW) + i);
#pragma unroll
    for (int i = 0; i < 6; i++) c[i] = __ldcs((const float4*)(base + 2 * XW) + i);

    float r0[24], r1[24], r2[24];
#pragma unroll
    for (int i = 0; i < 6; i++) {
        r0[4*i] = a[i].x; r0[4*i+1] = a[i].y; r0[4*i+2] = a[i].z; r0[4*i+3] = a[i].w;
        r1[4*i] = b[i].x; r1[4*i+1] = b[i].y; r1[4*i+2] = b[i].z; r1[4*i+3] = b[i].w;
        r2[4*i] = c[i].x; r2[4*i+1] = c[i].y; r2[4*i+2] = c[i].z; r2[4*i+3] = c[i].w;
    }

    float res[8];
#pragma unroll
    for (int j = 0; j < 8; j++) {
        res[j] = (k0 * r0[3*j] + k1 * r0[3*j+1] + k2 * r0[3*j+2]
                + k3 * r1[3*j] + k4 * r1[3*j+1] + k5 * r1[3*j+2]
                + k6 * r2[3*j] + k7 * r2[3*j+1] + k8 * r2[3*j+2]) * scale;
    }

    float4 o0 = make_float4(res[0], res[1], res[2], res[3]);
    float4 o1 = make_float4(res[4], res[5], res[6], res[7]);
    // output float4 index: (w*2048 + 8g)/4 = 2*idx
    __stcs((float4*)out + 2 * idx,     o0);
    __stcs((float4*)out + 2 * idx + 1, o1);
}

extern "C" void kernel_launch(void* const* d_in, const int* in_sizes, int n_in,
                              void* d_out, int out_size)
{
    const float* x   = (const float*)d_in[0];
    const float* wgt = (const float*)d_in[1];
    float* out = (float*)d_out;

    int total_threads = NH * GROUPS_PER_ROW;   // 524,288
    int block = 256;
    int grid = total_threads / block;          // 2048
    conv3x3_stride3_kernel<<<grid, block>>>(x, wgt, out);
}

// round 4
// speedup vs baseline: 1.0650x; 1.0569x over previous
#include <cuda_runtime.h>

// out[w*2048+h] = -dot(weight3x3, x[3w:3w+3, 3h:3h+3]) / 0.924458
// x: 6144x6144 fp32 -> out: 2048x2048 fp32. Pure HBM stream (168 MB).
// R1 shape (4 outputs/thread, 9 float4 loads, 1 float4 store) +
// persistent grid-stride (full residency, no wave-transition bubbles) +
// streaming store hint (keep L2 for read sectors).

#define XW 6144
#define NH 2048
#define GROUPS_PER_ROW 512          // NH / 4
#define TOTAL (NH * GROUPS_PER_ROW) // 1,048,576 work items

__global__ __launch_bounds__(256) void conv3x3_stride3_kernel(
    const float* __restrict__ x,
    const float* __restrict__ wgt,
    float* __restrict__ out)
{
    float k0 = wgt[0], k1 = wgt[1], k2 = wgt[2];
    float k3 = wgt[3], k4 = wgt[4], k5 = wgt[5];
    float k6 = wgt[6], k7 = wgt[7], k8 = wgt[8];
    const float scale = (float)(-1.0 / 0.924458);

    const int stride = gridDim.x * blockDim.x;   // 1184*256 = 303,104

    for (int idx = blockIdx.x * blockDim.x + threadIdx.x; idx < TOTAL; idx += stride) {
        int w = idx >> 9;                      // output row
        int g = idx & (GROUPS_PER_ROW - 1);    // group of 4 outputs

        const float* base = x + (size_t)(3 * w) * XW + 12 * g;  // 48B-aligned

        float4 a0 = *(const float4*)(base);
        float4 a1 = *(const float4*)(base + 4);
        float4 a2 = *(const float4*)(base + 8);
        float4 b0 = *(const float4*)(base + XW);
        float4 b1 = *(const float4*)(base + XW + 4);
        float4 b2 = *(const float4*)(base + XW + 8);
        float4 c0 = *(const float4*)(base + 2 * XW);
        float4 c1 = *(const float4*)(base + 2 * XW + 4);
        float4 c2 = *(const float4*)(base + 2 * XW + 8);

        float r0[12] = {a0.x, a0.y, a0.z, a0.w, a1.x, a1.y, a1.z, a1.w, a2.x, a2.y, a2.z, a2.w};
        float r1[12] = {b0.x, b0.y, b0.z, b0.w, b1.x, b1.y, b1.z, b1.w, b2.x, b2.y, b2.z, b2.w};
        float r2[12] = {c0.x, c0.y, c0.z, c0.w, c1.x, c1.y, c1.z, c1.w, c2.x, c2.y, c2.z, c2.w};

        float4 res;
        float* rp = (float*)&res;
#pragma unroll
        for (int j = 0; j < 4; j++) {
            rp[j] = (k0 * r0[3*j] + k1 * r0[3*j+1] + k2 * r0[3*j+2]
                   + k3 * r1[3*j] + k4 * r1[3*j+1] + k5 * r1[3*j+2]
                   + k6 * r2[3*j] + k7 * r2[3*j+1] + k8 * r2[3*j+2]) * scale;
        }

        __stcs((float4*)out + idx, res);
    }
}

extern "C" void kernel_launch(void* const* d_in, const int* in_sizes, int n_in,
                              void* d_out, int out_size)
{
    const float* x   = (const float*)d_in[0];
    const float* wgt = (const float*)d_in[1];
    float* out = (float*)d_out;

    // Full residency: 148 SMs x 8 CTAs (256 thr, 31 regs -> 8 CTAs/SM fits)
    int grid = 148 * 8;   // 1184
    conv3x3_stride3_kernel<<<grid, 256>>>(x, wgt, out);
}

// round 5
// speedup vs baseline: 1.0661x; 1.0010x over previous
#include <cuda_runtime.h>

// out[w*2048+h] = -dot(weight3x3, x[3w:3w+3, 3h:3h+3]) / 0.924458
// x: 6144x6144 fp32 -> out: 2048x2048 fp32. Pure HBM stream (168 MB).
// R1 shape (4 outputs/thread, 9 float4 loads, 1 float4 store) +
// persistent grid-stride (full residency, no wave-transition bubbles) +
// streaming store hint (keep L2 for read sectors).

#define XW 6144
#define NH 2048
#define GROUPS_PER_ROW 512          // NH / 4
#define TOTAL (NH * GROUPS_PER_ROW) // 1,048,576 work items

__global__ __launch_bounds__(256) void conv3x3_stride3_kernel(
    const float* __restrict__ x,
    const float* __restrict__ wgt,
    float* __restrict__ out)
{
    float k0 = wgt[0], k1 = wgt[1], k2 = wgt[2];
    float k3 = wgt[3], k4 = wgt[4], k5 = wgt[5];
    float k6 = wgt[6], k7 = wgt[7], k8 = wgt[8];
    const float scale = (float)(-1.0 / 0.924458);

    const int stride = gridDim.x * blockDim.x;   // 1184*256 = 303,104

    for (int idx = blockIdx.x * blockDim.x + threadIdx.x; idx < TOTAL; idx += stride) {
        int w = idx >> 9;                      // output row
        int g = idx & (GROUPS_PER_ROW - 1);    // group of 4 outputs

        const float* base = x + (size_t)(3 * w) * XW + 12 * g;  // 48B-aligned

        float4 a0 = *(const float4*)(base);
        float4 a1 = *(const float4*)(base + 4);
        float4 a2 = *(const float4*)(base + 8);
        float4 b0 = *(const float4*)(base + XW);
        float4 b1 = *(const float4*)(base + XW + 4);
        float4 b2 = *(const float4*)(base + XW + 8);
        float4 c0 = *(const float4*)(base + 2 * XW);
        float4 c1 = *(const float4*)(base + 2 * XW + 4);
        float4 c2 = *(const float4*)(base + 2 * XW + 8);

        float r0[12] = {a0.x, a0.y, a0.z, a0.w, a1.x, a1.y, a1.z, a1.w, a2.x, a2.y, a2.z, a2.w};
        float r1[12] = {b0.x, b0.y, b0.z, b0.w, b1.x, b1.y, b1.z, b1.w, b2.x, b2.y, b2.z, b2.w};
        float r2[12] = {c0.x, c0.y, c0.z, c0.w, c1.x, c1.y, c1.z, c1.w, c2.x, c2.y, c2.z, c2.w};

        float4 res;
        float* rp = (float*)&res;
#pragma unroll
        for (int j = 0; j < 4; j++) {
            rp[j] = (k0 * r0[3*j] + k1 * r0[3*j+1] + k2 * r0[3*j+2]
                   + k3 * r1[3*j] + k4 * r1[3*j+1] + k5 * r1[3*j+2]
                   + k6 * r2[3*j] + k7 * r2[3*j+1] + k8 * r2[3*j+2]) * scale;
        }

        __stcs((float4*)out + idx, res);
    }
}

extern "C" void kernel_launch(void* const* d_in, const int* in_sizes, int n_in,
                              void* d_out, int out_size)
{
    const float* x   = (const float*)d_in[0];
    const float* wgt = (const float*)d_in[1];
    float* out = (float*)d_out;

    // Full residency: 148 SMs x 8 CTAs (256 thr, 31 regs -> 8 CTAs/SM fits)
    int grid = 148 * 8;   // 1184
    conv3x3_stride3_kernel<<<grid, 256>>>(x, wgt, out);
}

// round 6
// speedup vs baseline: 1.1391x; 1.0685x over previous
#include <cuda_runtime.h>

// out[w*2048+h] = -dot(weight3x3, x[3w:3w+3, 3h:3h+3]) / 0.924458
// x: 6144x6144 fp32 -> out: 2048x2048 fp32. Pure HBM stream (168 MB).
// R1 shape exactly (4 outputs/thread, 9 float4 coalesced loads, 1 float4
// store, grid 4096 x 256, occ ~80%) + single change: streaming store hint
// (__stcs) so the never-re-read output doesn't write-allocate L2 ways,
// and scale pre-folded into the weights.

#define XW 6144
#define NH 2048
#define GROUPS_PER_ROW 512  // NH / 4

__global__ __launch_bounds__(256) void conv3x3_stride3_kernel(
    const float* __restrict__ x,
    const float* __restrict__ wgt,
    float* __restrict__ out)
{
    int idx = blockIdx.x * blockDim.x + threadIdx.x;   // 0 .. 2048*512-1
    int w = idx >> 9;                      // output row
    int g = idx & (GROUPS_PER_ROW - 1);    // horizontal group of 4 outputs

    const float scale = (float)(-1.0 / 0.924458);
    // fold scale into weights (uniform: 9 broadcast loads + 9 uniform FMULs)
    float k0 = wgt[0] * scale, k1 = wgt[1] * scale, k2 = wgt[2] * scale;
    float k3 = wgt[3] * scale, k4 = wgt[4] * scale, k5 = wgt[5] * scale;
    float k6 = wgt[6] * scale, k7 = wgt[7] * scale, k8 = wgt[8] * scale;

    // rows 3w..3w+2, starting column 12*g (48B-aligned)
    const float* base = x + (size_t)(3 * w) * XW + 12 * g;

    float4 a0 = *(const float4*)(base);
    float4 a1 = *(const float4*)(base + 4);
    float4 a2 = *(const float4*)(base + 8);
    float4 b0 = *(const float4*)(base + XW);
    float4 b1 = *(const float4*)(base + XW + 4);
    float4 b2 = *(const float4*)(base + XW + 8);
    float4 c0 = *(const float4*)(base + 2 * XW);
    float4 c1 = *(const float4*)(base + 2 * XW + 4);
    float4 c2 = *(const float4*)(base + 2 * XW + 8);

    float r0[12] = {a0.x, a0.y, a0.z, a0.w, a1.x, a1.y, a1.z, a1.w, a2.x, a2.y, a2.z, a2.w};
    float r1[12] = {b0.x, b0.y, b0.z, b0.w, b1.x, b1.y, b1.z, b1.w, b2.x, b2.y, b2.z, b2.w};
    float r2[12] = {c0.x, c0.y, c0.z, c0.w, c1.x, c1.y, c1.z, c1.w, c2.x, c2.y, c2.z, c2.w};

    float4 res;
    float* rp = (float*)&res;
#pragma unroll
    for (int j = 0; j < 4; j++) {
        rp[j] = k0 * r0[3*j] + k1 * r0[3*j+1] + k2 * r0[3*j+2]
              + k3 * r1[3*j] + k4 * r1[3*j+1] + k5 * r1[3*j+2]
              + k6 * r2[3*j] + k7 * r2[3*j+1] + k8 * r2[3*j+2];
    }

    // output float4 index == idx (w*512 + g)
    __stcs((float4*)out + idx, res);
}

extern "C" void kernel_launch(void* const* d_in, const int* in_sizes, int n_in,
                              void* d_out, int out_size)
{
    const float* x   = (const float*)d_in[0];
    const float* wgt = (const float*)d_in[1];
    float* out = (float*)d_out;

    int total_threads = NH * GROUPS_PER_ROW;   // 1,048,576
    int block = 256;
    int grid = total_threads / block;          // 4096
    conv3x3_stride3_kernel<<<grid, block>>>(x, wgt, out);
}